// round 5
// baseline (speedup 1.0000x reference)
#include <cuda_runtime.h>

// Dice score: input (B=4, C=5, 128^3) fp32 logits, target (4, 128^3) int ids.
// pred = argmax over C; per-batch/class counts of pred/target/intersection
// (classes 1..4); dice = (2I+eps)/(P+T+eps); mean of 16 values -> out[0].
//
// SINGLE kernel: ballot-histogram counting + global atomics + last-block
// finalize (threadfence-reduction pattern). The last block computes the
// scalar and re-zeroes g_cnt/g_ticket, so "scratch == 0 at entry" holds for
// every graph replay (deterministic, no call-count state).

#define NB 4
#define NC 5
#define NPOS (1 << 21)                   // 128^3
#define TPB 256
#define POS_PER_THREAD 16
#define POS_PER_BLOCK (TPB * POS_PER_THREAD)   // 4096, divides NPOS
#define NBLOCKS ((NB * NPOS) / POS_PER_BLOCK)  // 2048
#define NQUAD (POS_PER_THREAD / 4)             // 4

// flat: [b][kind*4 + (c-1)], kind 0=pred,1=tgt,2=inter. Zero at entry.
__device__ int g_cnt[NB * 12];
__device__ unsigned g_ticket;

__global__ void __launch_bounds__(TPB) k_count(const float* __restrict__ inp,
                                               const void* __restrict__ tgt,
                                               float* __restrict__ out) {
    __shared__ int s_cnt[12];
    __shared__ int s_is64;
    __shared__ int s_last;
    __shared__ int s_fin[NB * 12];
    const int tid  = threadIdx.x;
    const int lane = tid & 31;

    if (tid < 12) s_cnt[tid] = 0;
    if (tid < 32) {
        // Parallel dtype probe: one load + one ballot. int32 data read as
        // int64 puts a class id in the high word -> value >= 2^32 whenever
        // that word != 0. P(first 32 high words all zero) ~ (1/5)^32.
        long long v = ((const long long*)tgt)[tid];
        unsigned bad = __ballot_sync(0xffffffffu, v < 0 || v > (NC - 1));
        if (tid == 0) s_is64 = (bad == 0u);
    }
    __syncthreads();

    const long blockbase = (long)blockIdx.x * POS_PER_BLOCK;
    const int  b  = (int)(blockbase >> 21);
    const long n0 = (blockbase & (NPOS - 1)) + (long)tid * 4;
    const float* base = inp + (long)b * NC * NPOS + n0;
    const int is64 = s_is64;

    int pcnt[4] = {0, 0, 0, 0};
    int tcnt[4] = {0, 0, 0, 0};
    int icnt[4] = {0, 0, 0, 0};

    #pragma unroll
    for (int j = 0; j < NQUAD; j++) {
        // ---- targets: 4 positions ----
        const long gq = (blockbase >> 2) + (long)j * TPB + tid;  // quad index
        int tv[4];
        if (is64) {
            longlong4 t4 = ((const longlong4*)tgt)[gq];
            tv[0] = (int)t4.x; tv[1] = (int)t4.y; tv[2] = (int)t4.z; tv[3] = (int)t4.w;
        } else {
            int4 t4 = ((const int4*)tgt)[gq];
            tv[0] = t4.x; tv[1] = t4.y; tv[2] = t4.z; tv[3] = t4.w;
        }

        // ---- logits: 5 classes x float4 ----
        float va[NC][4];
        #pragma unroll
        for (int c = 0; c < NC; c++) {
            float4 v = *(const float4*)(base + (long)c * NPOS + (long)j * (TPB * 4));
            va[c][0] = v.x; va[c][1] = v.y; va[c][2] = v.z; va[c][3] = v.w;
        }

        // ---- per position: vmax + warp-ballot histogram ----
        #pragma unroll
        for (int k = 0; k < 4; k++) {
            const float f0 = va[0][k], f1 = va[1][k], f2 = va[2][k],
                        f3 = va[3][k], f4 = va[4][k];
            const float m = fmaxf(fmaxf(fmaxf(f0, f1), fmaxf(f2, f3)), f4);

            const unsigned pm1 = __ballot_sync(0xffffffffu, f1 == m);
            const unsigned pm2 = __ballot_sync(0xffffffffu, f2 == m);
            const unsigned pm3 = __ballot_sync(0xffffffffu, f3 == m);
            const unsigned pm4 = __ballot_sync(0xffffffffu, f4 == m);

            const int t = tv[k];
            const unsigned tm1 = __ballot_sync(0xffffffffu, t == 1);
            const unsigned tm2 = __ballot_sync(0xffffffffu, t == 2);
            const unsigned tm3 = __ballot_sync(0xffffffffu, t == 3);
            const unsigned tm4 = __ballot_sync(0xffffffffu, t == 4);

            pcnt[0] += __popc(pm1); pcnt[1] += __popc(pm2);
            pcnt[2] += __popc(pm3); pcnt[3] += __popc(pm4);
            tcnt[0] += __popc(tm1); tcnt[1] += __popc(tm2);
            tcnt[2] += __popc(tm3); tcnt[3] += __popc(tm4);
            icnt[0] += __popc(pm1 & tm1); icnt[1] += __popc(pm2 & tm2);
            icnt[2] += __popc(pm3 & tm3); icnt[3] += __popc(pm4 & tm4);
        }
    }

    // warp -> block: every lane holds identical ballot sums, lane 0 contributes
    if (lane == 0) {
        #pragma unroll
        for (int c = 0; c < 4; c++) {
            atomicAdd(&s_cnt[0 * 4 + c], pcnt[c]);
            atomicAdd(&s_cnt[1 * 4 + c], tcnt[c]);
            atomicAdd(&s_cnt[2 * 4 + c], icnt[c]);
        }
    }
    __syncthreads();

    // block -> global, then release-fence by the writers
    if (tid < 12) {
        atomicAdd(&g_cnt[b * 12 + tid], s_cnt[tid]);
        __threadfence();
    }
    __syncthreads();

    // last-block election
    if (tid == 0) s_last = (atomicAdd(&g_ticket, 1u) == NBLOCKS - 1);
    __syncthreads();

    if (s_last) {
        __threadfence();                  // acquire: see all blocks' counts
        if (tid < NB * 12) {
            s_fin[tid] = g_cnt[tid];
            g_cnt[tid] = 0;               // restore zero-at-entry invariant
        }
        if (tid == 0) g_ticket = 0u;
        __syncthreads();
        if (tid == 0) {
            float acc = 0.0f;
            #pragma unroll
            for (int bb = 0; bb < NB; bb++) {
                #pragma unroll
                for (int ci = 0; ci < 4; ci++) {
                    const float I = (float)s_fin[bb * 12 + 8 + ci];
                    const float U = (float)(s_fin[bb * 12 + ci] +
                                            s_fin[bb * 12 + 4 + ci]);
                    acc += (2.0f * I + 1e-5f) / (U + 1e-5f);
                }
            }
            out[0] = acc * (1.0f / 16.0f);
        }
    }
}

extern "C" void kernel_launch(void* const* d_in, const int* in_sizes, int n_in,
                              void* d_out, int out_size) {
    const float* inp = (const float*)d_in[0];
    const void*  tgt = d_in[1];
    float* out = (float*)d_out;
    (void)in_sizes; (void)n_in; (void)out_size;

    k_count<<<NBLOCKS, TPB>>>(inp, tgt, out);
}

// round 6
// speedup vs baseline: 1.3925x; 1.3925x over previous
#include <cuda_runtime.h>

// Dice score: input (B=4, C=5, 128^3) fp32 logits, target (4, 128^3) int ids.
// pred = argmax over C; per-batch/class counts of pred/target/intersection
// (classes 1..4); dice = (2I+eps)/(P+T+eps); mean of 16 values -> out[0].
//
// Single kernel. Per-thread byte-packed counters (class c-1 in byte c-1),
// 16-bit-field warp REDUX, shared atomics, returning global atomics
// (completion-ordered, no __threadfence / L1 flush), last-block finalize.
// Last block re-zeroes scratch so "scratch == 0 at entry" holds every replay.

#define NB 4
#define NC 5
#define NPOS (1 << 21)                   // 128^3
#define TPB 256
#define POS_PER_THREAD 16
#define POS_PER_BLOCK (TPB * POS_PER_THREAD)   // 4096, divides NPOS
#define NBLOCKS ((NB * NPOS) / POS_PER_BLOCK)  // 2048
#define NQUAD (POS_PER_THREAD / 4)             // 4

// flat: [b][kind*4 + (c-1)], kind 0=pred,1=tgt,2=inter. Zero at entry.
__device__ int g_cnt[NB * 12];
__device__ unsigned g_ticket;

__global__ void __launch_bounds__(TPB) k_count(const float* __restrict__ inp,
                                               const void* __restrict__ tgt,
                                               float* __restrict__ out) {
    // s_pack[kind*2 + h]: 16-bit fields, h=0 holds classes 1,3; h=1 holds 2,4
    __shared__ unsigned s_pack[6];
    __shared__ int s_is64;
    __shared__ int s_last;
    __shared__ int s_fin[NB * 12];
    volatile __shared__ int s_sink[12];
    const int tid  = threadIdx.x;
    const int lane = tid & 31;

    if (tid < 6) s_pack[tid] = 0;
    if (tid < 32) {
        // dtype probe: int32 read as int64 has a class id in the high word
        // whenever that word != 0; P(first 32 high words all zero) ~ (1/5)^32.
        long long v = ((const long long*)tgt)[tid];
        unsigned bad = __ballot_sync(0xffffffffu, v < 0 || v > (NC - 1));
        if (tid == 0) s_is64 = (bad == 0u);
    }
    __syncthreads();

    const long blockbase = (long)blockIdx.x * POS_PER_BLOCK;
    const int  b  = (int)(blockbase >> 21);
    const long n0 = (blockbase & (NPOS - 1)) + (long)tid * 4;
    const float* base = inp + (long)b * NC * NPOS + n0;
    const int is64 = s_is64;

    // byte-packed counters: byte (c-1) counts class c; max 16/byte
    unsigned pp = 0u, tp = 0u, ip = 0u;

    #pragma unroll
    for (int j = 0; j < NQUAD; j++) {
        // ---- targets: 4 positions ----
        const long gq = (blockbase >> 2) + (long)j * TPB + tid;  // quad index
        int tv[4];
        if (is64) {
            longlong4 t4 = ((const longlong4*)tgt)[gq];
            tv[0] = (int)t4.x; tv[1] = (int)t4.y; tv[2] = (int)t4.z; tv[3] = (int)t4.w;
        } else {
            int4 t4 = ((const int4*)tgt)[gq];
            tv[0] = t4.x; tv[1] = t4.y; tv[2] = t4.z; tv[3] = t4.w;
        }

        // ---- logits: 5 classes x float4 ----
        float va[NC][4];
        #pragma unroll
        for (int c = 0; c < NC; c++) {
            float4 v = *(const float4*)(base + (long)c * NPOS + (long)j * (TPB * 4));
            va[c][0] = v.x; va[c][1] = v.y; va[c][2] = v.z; va[c][3] = v.w;
        }

        // ---- per position: max + predicated packed increments ----
        #pragma unroll
        for (int k = 0; k < 4; k++) {
            const float f1 = va[1][k], f2 = va[2][k],
                        f3 = va[3][k], f4 = va[4][k];
            const float m = fmaxf(fmaxf(fmaxf(va[0][k], f1), fmaxf(f2, f3)), f4);
            const int t = tv[k];

            if (f1 == m) pp += 1u;
            if (f2 == m) pp += 1u << 8;
            if (f3 == m) pp += 1u << 16;
            if (f4 == m) pp += 1u << 24;

            if (t) tp += 1u << ((t - 1) * 8);

            if (f1 == m && t == 1) ip += 1u;
            if (f2 == m && t == 2) ip += 1u << 8;
            if (f3 == m && t == 3) ip += 1u << 16;
            if (f4 == m && t == 4) ip += 1u << 24;
        }
    }

    // warp reduction: split bytes into 16-bit fields (warp sum <= 512), REDUX
    {
        unsigned v[6];
        v[0] = pp & 0x00FF00FFu;  v[1] = (pp >> 8) & 0x00FF00FFu;
        v[2] = tp & 0x00FF00FFu;  v[3] = (tp >> 8) & 0x00FF00FFu;
        v[4] = ip & 0x00FF00FFu;  v[5] = (ip >> 8) & 0x00FF00FFu;
        #pragma unroll
        for (int i = 0; i < 6; i++)
            v[i] = __reduce_add_sync(0xffffffffu, v[i]);
        if (lane == 0) {
            #pragma unroll
            for (int i = 0; i < 6; i++) atomicAdd(&s_pack[i], v[i]);
        }
    }
    __syncthreads();

    // block -> global: returning atomics (completion = L2 updated), no fence
    if (tid < 12) {
        const int kind = tid >> 2;            // 0=pred,1=tgt,2=inter
        const int ci   = tid & 3;             // class-1
        const unsigned pk = s_pack[kind * 2 + (ci & 1)];
        const int cnt = (int)((pk >> (16 * (ci >> 1))) & 0xFFFFu);
        const int ret = atomicAdd(&g_cnt[b * 12 + tid], cnt);
        s_sink[tid] = ret;                    // consume: forces wait for ATOMG return
    }
    __syncthreads();

    // last-block election (all 12 adds of every arrived block are L2-complete)
    if (tid == 0) s_last = (atomicAdd(&g_ticket, 1u) == NBLOCKS - 1);
    __syncthreads();

    if (s_last) {
        if (tid < NB * 12) {
            s_fin[tid] = atomicAdd(&g_cnt[tid], 0);   // L2-coherent read
            g_cnt[tid] = 0;                           // zero-at-entry invariant
        }
        if (tid == 0) g_ticket = 0u;
        __syncthreads();
        if (tid == 0) {
            float acc = 0.0f;
            #pragma unroll
            for (int bb = 0; bb < NB; bb++) {
                #pragma unroll
                for (int ci = 0; ci < 4; ci++) {
                    const float I = (float)s_fin[bb * 12 + 8 + ci];
                    const float U = (float)(s_fin[bb * 12 + ci] +
                                            s_fin[bb * 12 + 4 + ci]);
                    acc += (2.0f * I + 1e-5f) / (U + 1e-5f);
                }
            }
            out[0] = acc * (1.0f / 16.0f);
        }
    }
}

extern "C" void kernel_launch(void* const* d_in, const int* in_sizes, int n_in,
                              void* d_out, int out_size) {
    const float* inp = (const float*)d_in[0];
    const void*  tgt = d_in[1];
    float* out = (float*)d_out;
    (void)in_sizes; (void)n_in; (void)out_size;

    k_count<<<NBLOCKS, TPB>>>(inp, tgt, out);
}